// round 4
// baseline (speedup 1.0000x reference)
#include <cuda_runtime.h>
#include <math.h>

#define BGR   32
#define NTOT  131072
#define NBLKX 2048
#define NBLKF 20

// ---------------- device scratch (no runtime alloc) ----------------
__device__ __align__(16) float g_x[(size_t)NTOT * 128];
__device__ __align__(16) float g_I[(size_t)NTOT * 40];
__device__ __align__(16) float g_ypre[1280 * 128];
__device__ __align__(16) float g_yp[BGR * 40 * 32];
__device__ __align__(16) float g_G[BGR * 32 * 32];
__device__ float g_part[NBLKX * 2];
__device__ float g_partf[NBLKF * 2];
__device__ float g_scal[4];
__device__ float g_sm[BGR * 64 * 40];
__device__ float g_ss[BGR * 64 * 40];
__device__ float g_m[BGR * 40];
__device__ float g_si[BGR * 40];

// =====================================================================
// K1: out[rows][128] = in[rows][64] @ W^T + b ; LN partial sums
// =====================================================================
struct SmG {
    float in_sh[64][68];
    float Wt[64][128];
    float bias[128];
    float red[16];
};

__global__ __launch_bounds__(256) void gemm_in_kernel(
    const float* __restrict__ inp, const float* __restrict__ Wg,
    const float* __restrict__ bg, int sel)
{
    extern __shared__ char smraw[];
    SmG& sm = *reinterpret_cast<SmG*>(smraw);
    const int t = threadIdx.x, w = t >> 5, l = t & 31;
    const size_t row0 = (size_t)blockIdx.x * 64;
    float* outp  = sel ? g_ypre : g_x;
    float* partp = sel ? g_partf : g_part;

#pragma unroll
    for (int u = 0; u < 4; ++u) {
        int id = t + 256 * u;
        int r = id >> 4, cq = id & 15;
        *reinterpret_cast<float4*>(&sm.in_sh[r][cq * 4]) =
            *reinterpret_cast<const float4*>(inp + (row0 + r) * 64 + cq * 4);
    }
#pragma unroll
    for (int u = 0; u < 32; ++u) {
        int id = t + 256 * u;
        int c = id >> 6, f = id & 63;
        sm.Wt[f][c] = Wg[id];
    }
    if (t < 128) sm.bias[t] = bg[t];
    __syncthreads();

    float acc[8][4];
#pragma unroll
    for (int r = 0; r < 8; ++r)
#pragma unroll
        for (int q = 0; q < 4; ++q) acc[r][q] = 0.f;

    for (int f4 = 0; f4 < 16; ++f4) {
        int f = f4 * 4;
        float wv[4][4];
#pragma unroll
        for (int i = 0; i < 4; ++i) {
            wv[0][i] = sm.Wt[f + i][l];
            wv[1][i] = sm.Wt[f + i][l + 32];
            wv[2][i] = sm.Wt[f + i][l + 64];
            wv[3][i] = sm.Wt[f + i][l + 96];
        }
#pragma unroll
        for (int r = 0; r < 8; ++r) {
            float4 xv = *reinterpret_cast<const float4*>(&sm.in_sh[w * 8 + r][f]);
#pragma unroll
            for (int q = 0; q < 4; ++q)
                acc[r][q] += xv.x * wv[q][0] + xv.y * wv[q][1] +
                             xv.z * wv[q][2] + xv.w * wv[q][3];
        }
    }

    float s1 = 0.f, s2 = 0.f;
#pragma unroll
    for (int r = 0; r < 8; ++r) {
        float* orow = outp + (row0 + w * 8 + r) * 128;
#pragma unroll
        for (int q = 0; q < 4; ++q) {
            float v = acc[r][q] + sm.bias[l + 32 * q];
            orow[l + 32 * q] = v;
            s1 += v; s2 += v * v;
        }
    }
#pragma unroll
    for (int o = 16; o; o >>= 1) {
        s1 += __shfl_xor_sync(0xffffffffu, s1, o);
        s2 += __shfl_xor_sync(0xffffffffu, s2, o);
    }
    if (l == 0) { sm.red[w] = s1; sm.red[8 + w] = s2; }
    __syncthreads();
    if (t == 0) {
        float S = 0.f, Q = 0.f;
        for (int i = 0; i < 8; ++i) { S += sm.red[i]; Q += sm.red[8 + i]; }
        partp[2 * blockIdx.x]     = S;
        partp[2 * blockIdx.x + 1] = Q;
    }
}

// =====================================================================
// K2: finalize LN scalars
// =====================================================================
__global__ void stats_kernel()
{
    __shared__ double sh[256];
    const int t = threadIdx.x;
    double s = 0.0, q = 0.0;
    for (int i = t; i < NBLKX; i += 256) { s += (double)g_part[2 * i]; q += (double)g_part[2 * i + 1]; }

    double S, Q, Sf, Qf;
    sh[t] = s; __syncthreads();
    for (int o = 128; o; o >>= 1) { if (t < o) sh[t] += sh[t + o]; __syncthreads(); }
    S = sh[0]; __syncthreads();

    sh[t] = q; __syncthreads();
    for (int o = 128; o; o >>= 1) { if (t < o) sh[t] += sh[t + o]; __syncthreads(); }
    Q = sh[0]; __syncthreads();

    sh[t] = (t < NBLKF) ? (double)g_partf[2 * t] : 0.0; __syncthreads();
    for (int o = 128; o; o >>= 1) { if (t < o) sh[t] += sh[t + o]; __syncthreads(); }
    Sf = sh[0]; __syncthreads();

    sh[t] = (t < NBLKF) ? (double)g_partf[2 * t + 1] : 0.0; __syncthreads();
    for (int o = 128; o; o >>= 1) { if (t < o) sh[t] += sh[t + o]; __syncthreads(); }
    Qf = sh[0];

    if (t == 0) {
        double nx = 16777216.0;
        double mx = S / nx, vx = Q / nx - mx * mx;
        g_scal[0] = (float)mx;
        g_scal[1] = (float)(1.0 / sqrt(vx + 1e-5));
        double ny = 163840.0;
        double my = Sf / ny, vy = Qf / ny - my * my;
        g_scal[2] = (float)my;
        g_scal[3] = (float)(1.0 / sqrt(vy + 1e-5));
    }
}

// =====================================================================
// K3: per graph: y_p = relu(q * relu(LN(ys) @ V)) ; G = y_p^T y_p
// =====================================================================
__global__ __launch_bounds__(256) void yp_kernel(
    const float* __restrict__ Vg, const float* __restrict__ qg)
{
    __shared__ float ys[40][128];
    __shared__ float yps[40][33];
    const int b = blockIdx.x, t = threadIdx.x;
    const float m = g_scal[2], rs = g_scal[3];
    for (int i = t; i < 5120; i += 256)
        ys[i >> 7][i & 127] = (g_ypre[b * 5120 + i] - m) * rs;
    __syncthreads();
#pragma unroll
    for (int u = 0; u < 5; ++u) {
        int id = t + 256 * u;
        int j = id >> 5, k = id & 31;
        float acc = 0.f;
        for (int c = 0; c < 128; ++c) acc += ys[j][c] * Vg[c * 32 + k];
        acc = fmaxf(acc, 0.f);
        acc = fmaxf(qg[k] * acc, 0.f);
        yps[j][k] = acc;
        g_yp[b * 1280 + id] = acc;
    }
    __syncthreads();
#pragma unroll
    for (int u = 0; u < 4; ++u) {
        int id = t + 256 * u;
        int k1 = id >> 5, k2 = id & 31;
        float acc = 0.f;
        for (int j = 0; j < 40; ++j) acc += yps[j][k1] * yps[j][k2];
        g_G[b * 1024 + id] = acc;
    }
}

// =====================================================================
// shared phase helpers (warp w owns rows w*8 .. w*8+7 of the 64-row tile)
// =====================================================================

// xp(:, l) = relu(x @ U)(:, l) into xpout[r][l]
template<int XPITCH>
__device__ __forceinline__ void phase_xp(const float (*xs)[128], const float (*U)[32],
                                         float (*xpout)[XPITCH], int w, int l)
{
    float acc[8];
#pragma unroll
    for (int r = 0; r < 8; ++r) acc[r] = 0.f;
    for (int c4 = 0; c4 < 32; ++c4) {
        int c = c4 * 4;
        float u0 = U[c][l], u1 = U[c + 1][l], u2 = U[c + 2][l], u3 = U[c + 3][l];
#pragma unroll
        for (int r = 0; r < 8; ++r) {
            float4 xv = *reinterpret_cast<const float4*>(&xs[w * 8 + r][c]);
            acc[r] += xv.x * u0 + xv.y * u1 + xv.z * u2 + xv.w * u3;
        }
    }
#pragma unroll
    for (int r = 0; r < 8; ++r) xpout[w * 8 + r][l] = fmaxf(acc[r], 0.f);
}

// I = xp @ yp^T -> g_I, plus per-tile softmax (m,s) partials
template<int XPITCH>
__device__ __forceinline__ void phase_I(const float (*xp)[XPITCH], const float (*yp)[33],
                                        size_t row0, int w, int l,
                                        float (*red_m)[40], float (*red_s)[40])
{
    const int j0 = l;
    const bool has1 = (l < 8);
    const int j1 = has1 ? (l + 32) : 39;
    float a0[8], a1[8];
#pragma unroll
    for (int r = 0; r < 8; ++r) { a0[r] = 0.f; a1[r] = 0.f; }
    for (int k4 = 0; k4 < 8; ++k4) {
        int k = k4 * 4;
        float y00 = yp[j0][k], y01 = yp[j0][k + 1], y02 = yp[j0][k + 2], y03 = yp[j0][k + 3];
        float y10 = yp[j1][k], y11 = yp[j1][k + 1], y12 = yp[j1][k + 2], y13 = yp[j1][k + 3];
#pragma unroll
        for (int r = 0; r < 8; ++r) {
            float4 xv = *reinterpret_cast<const float4*>(&xp[w * 8 + r][k]);
            a0[r] += xv.x * y00 + xv.y * y01 + xv.z * y02 + xv.w * y03;
            a1[r] += xv.x * y10 + xv.y * y11 + xv.z * y12 + xv.w * y13;
        }
    }
    float m0 = -1e30f, m1 = -1e30f;
#pragma unroll
    for (int r = 0; r < 8; ++r) { m0 = fmaxf(m0, a0[r]); m1 = fmaxf(m1, a1[r]); }
    float s0 = 0.f, s1v = 0.f;
#pragma unroll
    for (int r = 0; r < 8; ++r) { s0 += __expf(a0[r] - m0); s1v += __expf(a1[r] - m1); }
#pragma unroll
    for (int r = 0; r < 8; ++r) {
        size_t row = row0 + w * 8 + r;
        g_I[row * 40 + j0] = a0[r];
        if (has1) g_I[row * 40 + j1] = a1[r];
    }
    red_m[w][j0] = m0; red_s[w][j0] = s0;
    if (has1) { red_m[w][j1] = m1; red_s[w][j1] = s1v; }
}

__device__ __forceinline__ void phase_partial_out(const float (*red_m)[40],
                                                  const float (*red_s)[40],
                                                  int b, int blk, int t)
{
    if (t < 40) {
        float m = red_m[0][t], s = red_s[0][t];
#pragma unroll
        for (int ww = 1; ww < 8; ++ww) {
            float bm = red_m[ww][t], bs = red_s[ww][t];
            float mn = fmaxf(m, bm);
            s = s * __expf(m - mn) + bs * __expf(bm - mn);
            m = mn;
        }
        int idx = (b * 64 + blk) * 40 + t;
        g_sm[idx] = m; g_ss[idx] = s;
    }
}

// h = relu(A @ yp); lane owns k=l
__device__ __forceinline__ void phase_h(const float (*a)[44], const float (*yp)[33],
                                        float (*h)[36], int w, int l)
{
    float acc[8];
#pragma unroll
    for (int r = 0; r < 8; ++r) acc[r] = 0.f;
    for (int j4 = 0; j4 < 10; ++j4) {
        int j = j4 * 4;
        float y0 = yp[j][l], y1 = yp[j + 1][l], y2 = yp[j + 2][l], y3 = yp[j + 3][l];
#pragma unroll
        for (int r = 0; r < 8; ++r) {
            float4 av = *reinterpret_cast<const float4*>(&a[w * 8 + r][j]);
            acc[r] += av.x * y0 + av.y * y1 + av.z * y2 + av.w * y3;
        }
    }
#pragma unroll
    for (int r = 0; r < 8; ++r) h[w * 8 + r][l] = fmaxf(acc[r], 0.f);
}

// hc = h @ V^T ; gate ; update x (in smem, optionally write global)
__device__ __forceinline__ void phase_update(float (*xs)[128], const float (*h)[36],
                                             const float (*V)[33], const float* gw,
                                             float gb, size_t row0, int w, int l,
                                             bool write_global)
{
    float acc[8][4];
#pragma unroll
    for (int r = 0; r < 8; ++r)
#pragma unroll
        for (int q = 0; q < 4; ++q) acc[r][q] = 0.f;

    for (int k4 = 0; k4 < 8; ++k4) {
        int k = 4 * k4;
        float vv[4][4];
#pragma unroll
        for (int q = 0; q < 4; ++q) {
            int d = l + 32 * q;
            vv[q][0] = V[d][k];     vv[q][1] = V[d][k + 1];
            vv[q][2] = V[d][k + 2]; vv[q][3] = V[d][k + 3];
        }
#pragma unroll
        for (int r = 0; r < 8; ++r) {
            float4 hv = *reinterpret_cast<const float4*>(&h[w * 8 + r][k]);
#pragma unroll
            for (int q = 0; q < 4; ++q)
                acc[r][q] += hv.x * vv[q][0] + hv.y * vv[q][1] +
                             hv.z * vv[q][2] + hv.w * vv[q][3];
        }
    }
#pragma unroll
    for (int r = 0; r < 8; ++r) {
        float gp = 0.f;
        float xv[4];
#pragma unroll
        for (int q = 0; q < 4; ++q) {
            int d = l + 32 * q;
            xv[q] = xs[w * 8 + r][d];
            gp += xv[q] * gw[d] + acc[r][q] * gw[128 + d];
        }
#pragma unroll
        for (int o = 16; o; o >>= 1) gp += __shfl_xor_sync(0xffffffffu, gp, o);
        float z = 1.f / (1.f + __expf(-(gp + gb)));
        float* orow = g_x + (row0 + w * 8 + r) * 128;
#pragma unroll
        for (int q = 0; q < 4; ++q) {
            int d = l + 32 * q;
            float nv = (1.f - z) * xv[q] + z * acc[r][q];
            xs[w * 8 + r][d] = nv;
            if (write_global) orow[d] = nv;
        }
    }
}

// =====================================================================
// K4: layerA0 — normalize x (write back), xp0, I0, softmax partials
// =====================================================================
struct SmA {
    float xs[64][128];
    float U[128][32];
    float yp[40][33];
    float xp[64][36];
    float red_m[8][40];
    float red_s[8][40];
};

__global__ __launch_bounds__(256) void layerA0_kernel(const float* __restrict__ Ug)
{
    extern __shared__ char smraw[];
    SmA& sm = *reinterpret_cast<SmA*>(smraw);
    const int t = threadIdx.x, w = t >> 5, l = t & 31;
    const size_t row0 = (size_t)blockIdx.x * 64;
    const int b = blockIdx.x >> 6, blk = blockIdx.x & 63;
    const float m = g_scal[0], rs = g_scal[1];

#pragma unroll
    for (int u = 0; u < 8; ++u) {
        int id = t + 256 * u;
        int r = id >> 5, cq = id & 31;
        float* gp = g_x + (row0 + r) * 128 + cq * 4;
        float4 v = *reinterpret_cast<const float4*>(gp);
        v.x = (v.x - m) * rs; v.y = (v.y - m) * rs;
        v.z = (v.z - m) * rs; v.w = (v.w - m) * rs;
        *reinterpret_cast<float4*>(gp) = v;                 // normalized write-back
        *reinterpret_cast<float4*>(&sm.xs[r][cq * 4]) = v;
    }
#pragma unroll
    for (int u = 0; u < 4; ++u) {
        int id = t + 256 * u;
        int c = id >> 3, kq = id & 7;
        *reinterpret_cast<float4*>(&sm.U[c][kq * 4]) =
            *reinterpret_cast<const float4*>(Ug + c * 32 + kq * 4);
    }
#pragma unroll
    for (int u = 0; u < 5; ++u) {
        int id = t + 256 * u;
        sm.yp[id >> 5][id & 31] = g_yp[b * 1280 + id];
    }
    __syncthreads();

    phase_xp<36>(sm.xs, sm.U, sm.xp, w, l);
    __syncwarp();
    phase_I<36>(sm.xp, sm.yp, row0, w, l, sm.red_m, sm.red_s);
    __syncthreads();
    phase_partial_out(sm.red_m, sm.red_s, b, blk, t);
}

// =====================================================================
// K5: merge softmax partials
// =====================================================================
__global__ void merge_kernel()
{
    const int b = blockIdx.x, t = threadIdx.x;
    if (t >= 40) return;
    float m = -1e30f, s = 0.f;
    for (int blk = 0; blk < 64; ++blk) {
        int idx = (b * 64 + blk) * 40 + t;
        float bm = g_sm[idx], bs = g_ss[idx];
        float mn = fmaxf(m, bm);
        s = s * __expf(m - mn) + bs * __expf(bm - mn);
        m = mn;
    }
    g_m[b * 40 + t]  = m;
    g_si[b * 40 + t] = 1.f / s;
}

// =====================================================================
// K6: BA — layerB(il) fused with layerA(il+1)
// =====================================================================
struct SmBA {
    float xs[64][128];
    float a[64][44];
    float yp[40][33];
    float V[128][33];
    float U[128][32];
    float h[64][36];
    float gw[256];
    float gb;
    float red_m[8][40];
    float red_s[8][40];
};

__global__ __launch_bounds__(256) void BA_kernel(
    const float* __restrict__ Vg, const float* __restrict__ Ug,
    const float* __restrict__ gWp, const float* __restrict__ gBp)
{
    extern __shared__ char smraw[];
    SmBA& sm = *reinterpret_cast<SmBA*>(smraw);
    const int t = threadIdx.x, w = t >> 5, l = t & 31;
    const size_t row0 = (size_t)blockIdx.x * 64;
    const int b = blockIdx.x >> 6, blk = blockIdx.x & 63;

#pragma unroll
    for (int u = 0; u < 8; ++u) {
        int id = t + 256 * u;
        int r = id >> 5, cq = id & 31;
        *reinterpret_cast<float4*>(&sm.xs[r][cq * 4]) =
            *reinterpret_cast<const float4*>(g_x + (row0 + r) * 128 + cq * 4);
    }
#pragma unroll
    for (int u = 0; u < 16; ++u) {
        int id = t + 256 * u;
        sm.V[id >> 5][id & 31] = Vg[id];
    }
#pragma unroll
    for (int u = 0; u < 4; ++u) {
        int id = t + 256 * u;
        int c = id >> 3, kq = id & 7;
        *reinterpret_cast<float4*>(&sm.U[c][kq * 4]) =
            *reinterpret_cast<const float4*>(Ug + c * 32 + kq * 4);
    }
#pragma unroll
    for (int u = 0; u < 5; ++u) {
        int id = t + 256 * u;
        sm.yp[id >> 5][id & 31] = g_yp[b * 1280 + id];
    }
    sm.gw[t] = gWp[t];
    if (t == 0) sm.gb = gBp[0];
#pragma unroll
    for (int u = 0; u < 10; ++u) {
        int id = t + 256 * u;
        int r = id / 40, j = id - r * 40;
        float v = g_I[row0 * 40 + id];
        sm.a[r][j] = __expf(v - g_m[b * 40 + j]) * g_si[b * 40 + j];
    }
    __syncthreads();

    phase_h(sm.a, sm.yp, sm.h, w, l);
    __syncwarp();
    phase_update(sm.xs, sm.h, sm.V, sm.gw, sm.gb, row0, w, l, true);
    __syncwarp();
    phase_xp<36>(sm.xs, sm.U, sm.h, w, l);     // reuse h buffer as xp
    __syncwarp();
    phase_I<36>(sm.h, sm.yp, row0, w, l, sm.red_m, sm.red_s);
    __syncthreads();
    phase_partial_out(sm.red_m, sm.red_s, b, blk, t);
}

// =====================================================================
// K7: BF — layerB(last) fused with final output (no g_x / g_I writes)
// =====================================================================
struct SmBF {
    float xs[64][128];
    float a[64][44];
    float yp[40][33];
    float V[128][33];
    float U[128][32];
    float G[32][32];
    float h[64][36];
    float gw[256];
    float gb;
};

__global__ __launch_bounds__(256) void BF_kernel(
    const float* __restrict__ Vg, const float* __restrict__ Ug,
    const float* __restrict__ gWp, const float* __restrict__ gBp,
    float* __restrict__ out)
{
    extern __shared__ char smraw[];
    SmBF& sm = *reinterpret_cast<SmBF*>(smraw);
    const int t = threadIdx.x, w = t >> 5, l = t & 31;
    const size_t row0 = (size_t)blockIdx.x * 64;
    const int b = blockIdx.x >> 6;

#pragma unroll
    for (int u = 0; u < 8; ++u) {
        int id = t + 256 * u;
        int r = id >> 5, cq = id & 31;
        *reinterpret_cast<float4*>(&sm.xs[r][cq * 4]) =
            *reinterpret_cast<const float4*>(g_x + (row0 + r) * 128 + cq * 4);
    }
#pragma unroll
    for (int u = 0; u < 16; ++u) {
        int id = t + 256 * u;
        sm.V[id >> 5][id & 31] = Vg[id];
    }
#pragma unroll
    for (int u = 0; u < 4; ++u) {
        int id = t + 256 * u;
        int c = id >> 3, kq = id & 7;
        *reinterpret_cast<float4*>(&sm.U[c][kq * 4]) =
            *reinterpret_cast<const float4*>(Ug + c * 32 + kq * 4);
    }
    {
        int k1 = t >> 3;
        *reinterpret_cast<float4*>(&sm.G[k1][(t & 7) * 4]) =
            *reinterpret_cast<const float4*>(g_G + b * 1024 + t * 4);
    }
#pragma unroll
    for (int u = 0; u < 5; ++u) {
        int id = t + 256 * u;
        sm.yp[id >> 5][id & 31] = g_yp[b * 1280 + id];
    }
    sm.gw[t] = gWp[t];
    if (t == 0) sm.gb = gBp[0];
#pragma unroll
    for (int u = 0; u < 10; ++u) {
        int id = t + 256 * u;
        int r = id / 40, j = id - r * 40;
        float v = g_I[row0 * 40 + id];
        sm.a[r][j] = __expf(v - g_m[b * 40 + j]) * g_si[b * 40 + j];
    }
    __syncthreads();

    phase_h(sm.a, sm.yp, sm.h, w, l);
    __syncwarp();
    phase_update(sm.xs, sm.h, sm.V, sm.gw, sm.gb, row0, w, l, false);
    __syncwarp();
    phase_xp<36>(sm.xs, sm.U, sm.h, w, l);     // reuse h buffer as xp
    __syncwarp();

    // out = sigmoid(xp^T G xp) per row
    {
        float acc[8];
#pragma unroll
        for (int r = 0; r < 8; ++r) acc[r] = 0.f;
        for (int k14 = 0; k14 < 8; ++k14) {
            int k1 = 4 * k14;
            float g0 = sm.G[k1][l], g1 = sm.G[k1 + 1][l],
                  g2 = sm.G[k1 + 2][l], g3 = sm.G[k1 + 3][l];
#pragma unroll
            for (int r = 0; r < 8; ++r) {
                float4 xv = *reinterpret_cast<const float4*>(&sm.h[w * 8 + r][k1]);
                acc[r] += xv.x * g0 + xv.y * g1 + xv.z * g2 + xv.w * g3;
            }
        }
#pragma unroll
        for (int r = 0; r < 8; ++r) {
            float v = sm.h[w * 8 + r][l] * acc[r];
#pragma unroll
            for (int o = 16; o; o >>= 1) v += __shfl_xor_sync(0xffffffffu, v, o);
            if (l == 0) out[row0 + w * 8 + r] = 1.f / (1.f + __expf(-v));
        }
    }
}

// =====================================================================
extern "C" void kernel_launch(void* const* d_in, const int* in_sizes, int n_in,
                              void* d_out, int out_size)
{
    const float* node = (const float*)d_in[0];
    const float* frag = (const float*)d_in[1];
    const float* Wg   = (const float*)d_in[2];
    const float* bg   = (const float*)d_in[3];
    const float* Ug   = (const float*)d_in[4];
    const float* Vg   = (const float*)d_in[5];
    const float* qg   = (const float*)d_in[6];
    const float* gW   = (const float*)d_in[7];
    const float* gB   = (const float*)d_in[8];
    float* out = (float*)d_out;

    cudaFuncSetAttribute(gemm_in_kernel, cudaFuncAttributeMaxDynamicSharedMemorySize, (int)sizeof(SmG));
    cudaFuncSetAttribute(layerA0_kernel, cudaFuncAttributeMaxDynamicSharedMemorySize, (int)sizeof(SmA));
    cudaFuncSetAttribute(BA_kernel,      cudaFuncAttributeMaxDynamicSharedMemorySize, (int)sizeof(SmBA));
    cudaFuncSetAttribute(BF_kernel,      cudaFuncAttributeMaxDynamicSharedMemorySize, (int)sizeof(SmBF));

    gemm_in_kernel<<<NBLKX, 256, sizeof(SmG)>>>(node, Wg, bg, 0);
    gemm_in_kernel<<<NBLKF, 256, sizeof(SmG)>>>(frag, Wg, bg, 1);
    stats_kernel<<<1, 256>>>();
    yp_kernel<<<BGR, 256>>>(Vg, qg);
    layerA0_kernel<<<NBLKX, 256, sizeof(SmA)>>>(Ug);
    merge_kernel<<<BGR, 64>>>();
    BA_kernel<<<NBLKX, 256, sizeof(SmBA)>>>(Vg, Ug, gW, gB);
    merge_kernel<<<BGR, 64>>>();
    BF_kernel<<<NBLKX, 256, sizeof(SmBF)>>>(Vg, Ug, gW, gB, out);
}

// round 5
// speedup vs baseline: 1.5749x; 1.5749x over previous
#include <cuda_runtime.h>
#include <math.h>

#define BGR   32
#define NTOT  131072
#define NBLKX 2048
#define NBLKF 20

// ---------------- device scratch (no runtime alloc) ----------------
__device__ __align__(16) float g_x[(size_t)NTOT * 128];
__device__ __align__(16) float g_I[(size_t)NTOT * 40];
__device__ __align__(16) float g_ypre[1280 * 128];
__device__ __align__(16) float g_yp[BGR * 40 * 32];
__device__ __align__(16) float g_G[BGR * 32 * 32];
__device__ float g_part[NBLKX * 2];
__device__ float g_partf[NBLKF * 2];
__device__ float g_scal[4];
__device__ float g_sm[BGR * 64 * 40];
__device__ float g_ss[BGR * 64 * 40];
__device__ float g_m[BGR * 40];
__device__ float g_si[BGR * 40];

// =====================================================================
// K1: out[rows][128] = in[rows][64] @ W^T + b ; LN partial sums
// =====================================================================
struct SmG {
    float in_sh[64][68];
    float Wt[64][128];
    float bias[128];
    float red[16];
};

__global__ __launch_bounds__(256) void gemm_in_kernel(
    const float* __restrict__ inp, const float* __restrict__ Wg,
    const float* __restrict__ bg, int sel)
{
    extern __shared__ char smraw[];
    SmG& sm = *reinterpret_cast<SmG*>(smraw);
    const int t = threadIdx.x, w = t >> 5, l = t & 31;
    const size_t row0 = (size_t)blockIdx.x * 64;
    float* outp  = sel ? g_ypre : g_x;
    float* partp = sel ? g_partf : g_part;

#pragma unroll
    for (int u = 0; u < 4; ++u) {
        int id = t + 256 * u;
        int r = id >> 4, cq = id & 15;
        *reinterpret_cast<float4*>(&sm.in_sh[r][cq * 4]) =
            *reinterpret_cast<const float4*>(inp + (row0 + r) * 64 + cq * 4);
    }
#pragma unroll
    for (int u = 0; u < 32; ++u) {
        int id = t + 256 * u;
        int c = id >> 6, f = id & 63;
        sm.Wt[f][c] = Wg[id];
    }
    if (t < 128) sm.bias[t] = bg[t];
    __syncthreads();

    float acc[8][4];
#pragma unroll
    for (int r = 0; r < 8; ++r)
#pragma unroll
        for (int q = 0; q < 4; ++q) acc[r][q] = 0.f;

    for (int f4 = 0; f4 < 16; ++f4) {
        int f = f4 * 4;
        float wv[4][4];
#pragma unroll
        for (int i = 0; i < 4; ++i) {
            wv[0][i] = sm.Wt[f + i][l];
            wv[1][i] = sm.Wt[f + i][l + 32];
            wv[2][i] = sm.Wt[f + i][l + 64];
            wv[3][i] = sm.Wt[f + i][l + 96];
        }
#pragma unroll
        for (int r = 0; r < 8; ++r) {
            float4 xv = *reinterpret_cast<const float4*>(&sm.in_sh[w * 8 + r][f]);
#pragma unroll
            for (int q = 0; q < 4; ++q)
                acc[r][q] += xv.x * wv[q][0] + xv.y * wv[q][1] +
                             xv.z * wv[q][2] + xv.w * wv[q][3];
        }
    }

    float s1 = 0.f, s2 = 0.f;
#pragma unroll
    for (int r = 0; r < 8; ++r) {
        float* orow = outp + (row0 + w * 8 + r) * 128;
#pragma unroll
        for (int q = 0; q < 4; ++q) {
            float v = acc[r][q] + sm.bias[l + 32 * q];
            orow[l + 32 * q] = v;
            s1 += v; s2 += v * v;
        }
    }
#pragma unroll
    for (int o = 16; o; o >>= 1) {
        s1 += __shfl_xor_sync(0xffffffffu, s1, o);
        s2 += __shfl_xor_sync(0xffffffffu, s2, o);
    }
    if (l == 0) { sm.red[w] = s1; sm.red[8 + w] = s2; }
    __syncthreads();
    if (t == 0) {
        float S = 0.f, Q = 0.f;
        for (int i = 0; i < 8; ++i) { S += sm.red[i]; Q += sm.red[8 + i]; }
        partp[2 * blockIdx.x]     = S;
        partp[2 * blockIdx.x + 1] = Q;
    }
}

// =====================================================================
// K2: finalize LN scalars
// =====================================================================
__global__ void stats_kernel()
{
    __shared__ double sh[256];
    const int t = threadIdx.x;
    double s = 0.0, q = 0.0;
    for (int i = t; i < NBLKX; i += 256) { s += (double)g_part[2 * i]; q += (double)g_part[2 * i + 1]; }

    double S, Q, Sf, Qf;
    sh[t] = s; __syncthreads();
    for (int o = 128; o; o >>= 1) { if (t < o) sh[t] += sh[t + o]; __syncthreads(); }
    S = sh[0]; __syncthreads();

    sh[t] = q; __syncthreads();
    for (int o = 128; o; o >>= 1) { if (t < o) sh[t] += sh[t + o]; __syncthreads(); }
    Q = sh[0]; __syncthreads();

    sh[t] = (t < NBLKF) ? (double)g_partf[2 * t] : 0.0; __syncthreads();
    for (int o = 128; o; o >>= 1) { if (t < o) sh[t] += sh[t + o]; __syncthreads(); }
    Sf = sh[0]; __syncthreads();

    sh[t] = (t < NBLKF) ? (double)g_partf[2 * t + 1] : 0.0; __syncthreads();
    for (int o = 128; o; o >>= 1) { if (t < o) sh[t] += sh[t + o]; __syncthreads(); }
    Qf = sh[0];

    if (t == 0) {
        double nx = 16777216.0;
        double mx = S / nx, vx = Q / nx - mx * mx;
        g_scal[0] = (float)mx;
        g_scal[1] = (float)(1.0 / sqrt(vx + 1e-5));
        double ny = 163840.0;
        double my = Sf / ny, vy = Qf / ny - my * my;
        g_scal[2] = (float)my;
        g_scal[3] = (float)(1.0 / sqrt(vy + 1e-5));
    }
}

// =====================================================================
// K3: per graph: y_p = relu(q * relu(LN(ys) @ V)) (V cached in smem)
// =====================================================================
__global__ __launch_bounds__(256) void yp_kernel(
    const float* __restrict__ Vg, const float* __restrict__ qg)
{
    __shared__ float ys[40][128];
    __shared__ float Vs[128][33];
    __shared__ float qs[32];
    const int b = blockIdx.x, t = threadIdx.x;
    const float m = g_scal[2], rs = g_scal[3];
    for (int i = t; i < 5120; i += 256)
        ys[i >> 7][i & 127] = (g_ypre[b * 5120 + i] - m) * rs;
#pragma unroll
    for (int u = 0; u < 16; ++u) {
        int id = t + 256 * u;
        Vs[id >> 5][id & 31] = Vg[id];
    }
    if (t < 32) qs[t] = qg[t];
    __syncthreads();
#pragma unroll
    for (int u = 0; u < 5; ++u) {
        int id = t + 256 * u;
        int j = id >> 5, k = id & 31;
        float acc = 0.f;
#pragma unroll
        for (int c = 0; c < 128; ++c) acc += ys[j][c] * Vs[c][k];
        acc = fmaxf(acc, 0.f);
        acc = fmaxf(qs[k] * acc, 0.f);
        g_yp[b * 1280 + id] = acc;
    }
}

// =====================================================================
// K3b: per graph Gram G = y_p^T y_p
// =====================================================================
__global__ __launch_bounds__(256) void gram_kernel()
{
    __shared__ float yps[40][33];
    const int b = blockIdx.x, t = threadIdx.x;
#pragma unroll
    for (int u = 0; u < 5; ++u) {
        int id = t + 256 * u;
        yps[id >> 5][id & 31] = g_yp[b * 1280 + id];
    }
    __syncthreads();
#pragma unroll
    for (int u = 0; u < 4; ++u) {
        int id = t + 256 * u;
        int k1 = id >> 5, k2 = id & 31;
        float acc = 0.f;
#pragma unroll
        for (int j = 0; j < 40; ++j) acc += yps[j][k1] * yps[j][k2];
        g_G[b * 1024 + id] = acc;
    }
}

// =====================================================================
// K4: layerA — (optional norm+writeback), xp = relu(x@U), I = xp@yp^T,
//              per-tile softmax partials
// =====================================================================
struct SmA {
    float xs[64][128];
    float U[128][32];
    float yp[40][33];
    float xp[64][36];
    float red_m[8][40];
    float red_s[8][40];
};

__global__ __launch_bounds__(256) void layerA_kernel(const float* __restrict__ Ug,
                                                     int do_norm)
{
    extern __shared__ char smraw[];
    SmA& sm = *reinterpret_cast<SmA*>(smraw);
    const int t = threadIdx.x, w = t >> 5, l = t & 31;
    const size_t row0 = (size_t)blockIdx.x * 64;
    const int b = blockIdx.x >> 6, blk = blockIdx.x & 63;

    if (do_norm) {
        const float m = g_scal[0], rs = g_scal[1];
#pragma unroll
        for (int u = 0; u < 8; ++u) {
            int id = t + 256 * u;
            int r = id >> 5, cq = id & 31;
            float* gp = g_x + (row0 + r) * 128 + cq * 4;
            float4 v = *reinterpret_cast<const float4*>(gp);
            v.x = (v.x - m) * rs; v.y = (v.y - m) * rs;
            v.z = (v.z - m) * rs; v.w = (v.w - m) * rs;
            *reinterpret_cast<float4*>(gp) = v;
            *reinterpret_cast<float4*>(&sm.xs[r][cq * 4]) = v;
        }
    } else {
#pragma unroll
        for (int u = 0; u < 8; ++u) {
            int id = t + 256 * u;
            int r = id >> 5, cq = id & 31;
            *reinterpret_cast<float4*>(&sm.xs[r][cq * 4]) =
                *reinterpret_cast<const float4*>(g_x + (row0 + r) * 128 + cq * 4);
        }
    }
#pragma unroll
    for (int u = 0; u < 4; ++u) {
        int id = t + 256 * u;
        int c = id >> 3, kq = id & 7;
        *reinterpret_cast<float4*>(&sm.U[c][kq * 4]) =
            *reinterpret_cast<const float4*>(Ug + c * 32 + kq * 4);
    }
#pragma unroll
    for (int u = 0; u < 5; ++u) {
        int id = t + 256 * u;
        sm.yp[id >> 5][id & 31] = g_yp[b * 1280 + id];
    }
    __syncthreads();

    // xp = relu(x @ U); lane owns k=l
    {
        float acc[8];
#pragma unroll
        for (int r = 0; r < 8; ++r) acc[r] = 0.f;
        for (int c4 = 0; c4 < 32; ++c4) {
            int c = c4 * 4;
            float u0 = sm.U[c][l], u1 = sm.U[c + 1][l],
                  u2 = sm.U[c + 2][l], u3 = sm.U[c + 3][l];
#pragma unroll
            for (int r = 0; r < 8; ++r) {
                float4 xv = *reinterpret_cast<const float4*>(&sm.xs[w * 8 + r][c]);
                acc[r] += xv.x * u0 + xv.y * u1 + xv.z * u2 + xv.w * u3;
            }
        }
#pragma unroll
        for (int r = 0; r < 8; ++r) sm.xp[w * 8 + r][l] = fmaxf(acc[r], 0.f);
    }
    __syncwarp();

    // I = xp @ yp^T; lane handles j0=l and (if l<8) j1=l+32
    {
        const int j0 = l;
        const bool has1 = (l < 8);
        const int j1 = has1 ? (l + 32) : 39;
        float a0[8], a1[8];
#pragma unroll
        for (int r = 0; r < 8; ++r) { a0[r] = 0.f; a1[r] = 0.f; }
        for (int k4 = 0; k4 < 8; ++k4) {
            int k = k4 * 4;
            float y00 = sm.yp[j0][k], y01 = sm.yp[j0][k + 1],
                  y02 = sm.yp[j0][k + 2], y03 = sm.yp[j0][k + 3];
            float y10 = sm.yp[j1][k], y11 = sm.yp[j1][k + 1],
                  y12 = sm.yp[j1][k + 2], y13 = sm.yp[j1][k + 3];
#pragma unroll
            for (int r = 0; r < 8; ++r) {
                float4 xv = *reinterpret_cast<const float4*>(&sm.xp[w * 8 + r][k]);
                a0[r] += xv.x * y00 + xv.y * y01 + xv.z * y02 + xv.w * y03;
                a1[r] += xv.x * y10 + xv.y * y11 + xv.z * y12 + xv.w * y13;
            }
        }
        float m0 = -1e30f, m1 = -1e30f;
#pragma unroll
        for (int r = 0; r < 8; ++r) { m0 = fmaxf(m0, a0[r]); m1 = fmaxf(m1, a1[r]); }
        float s0 = 0.f, s1v = 0.f;
#pragma unroll
        for (int r = 0; r < 8; ++r) { s0 += __expf(a0[r] - m0); s1v += __expf(a1[r] - m1); }
#pragma unroll
        for (int r = 0; r < 8; ++r) {
            size_t row = row0 + w * 8 + r;
            g_I[row * 40 + j0] = a0[r];
            if (has1) g_I[row * 40 + j1] = a1[r];
        }
        sm.red_m[w][j0] = m0; sm.red_s[w][j0] = s0;
        if (has1) { sm.red_m[w][j1] = m1; sm.red_s[w][j1] = s1v; }
    }
    __syncthreads();

    if (t < 40) {
        float m = sm.red_m[0][t], s = sm.red_s[0][t];
#pragma unroll
        for (int ww = 1; ww < 8; ++ww) {
            float bm = sm.red_m[ww][t], bs = sm.red_s[ww][t];
            float mn = fmaxf(m, bm);
            s = s * __expf(m - mn) + bs * __expf(bm - mn);
            m = mn;
        }
        int idx = (b * 64 + blk) * 40 + t;
        g_sm[idx] = m; g_ss[idx] = s;
    }
}

// =====================================================================
// K5: merge softmax partials
// =====================================================================
__global__ void merge_kernel()
{
    const int b = blockIdx.x, t = threadIdx.x;
    if (t >= 40) return;
    float m = -1e30f, s = 0.f;
    for (int blk = 0; blk < 64; ++blk) {
        int idx = (b * 64 + blk) * 40 + t;
        float bm = g_sm[idx], bs = g_ss[idx];
        float mn = fmaxf(m, bm);
        s = s * __expf(m - mn) + bs * __expf(bm - mn);
        m = mn;
    }
    g_m[b * 40 + t]  = m;
    g_si[b * 40 + t] = 1.f / s;
}

// =====================================================================
// K6: layerB — A, h=relu(A@yp), hc=h@V^T, gate, x-update
// =====================================================================
struct SmB {
    float xs[64][128];
    float a[64][44];
    float yp[40][33];
    float V[128][33];
    float h[64][36];
    float gw[256];
    float gb;
};

__global__ __launch_bounds__(256) void layerB_kernel(
    const float* __restrict__ Vg, const float* __restrict__ gWp,
    const float* __restrict__ gBp)
{
    extern __shared__ char smraw[];
    SmB& sm = *reinterpret_cast<SmB*>(smraw);
    const int t = threadIdx.x, w = t >> 5, l = t & 31;
    const size_t row0 = (size_t)blockIdx.x * 64;
    const int b = blockIdx.x >> 6;

#pragma unroll
    for (int u = 0; u < 8; ++u) {
        int id = t + 256 * u;
        int r = id >> 5, cq = id & 31;
        *reinterpret_cast<float4*>(&sm.xs[r][cq * 4]) =
            *reinterpret_cast<const float4*>(g_x + (row0 + r) * 128 + cq * 4);
    }
#pragma unroll
    for (int u = 0; u < 16; ++u) {
        int id = t + 256 * u;
        sm.V[id >> 5][id & 31] = Vg[id];
    }
#pragma unroll
    for (int u = 0; u < 5; ++u) {
        int id = t + 256 * u;
        sm.yp[id >> 5][id & 31] = g_yp[b * 1280 + id];
    }
    sm.gw[t] = gWp[t];
    if (t == 0) sm.gb = gBp[0];
#pragma unroll
    for (int u = 0; u < 10; ++u) {
        int id = t + 256 * u;
        int r = id / 40, j = id - r * 40;
        float v = g_I[row0 * 40 + id];
        sm.a[r][j] = __expf(v - g_m[b * 40 + j]) * g_si[b * 40 + j];
    }
    __syncthreads();

    // h = relu(A @ yp); lane owns k=l
    {
        float acc[8];
#pragma unroll
        for (int r = 0; r < 8; ++r) acc[r] = 0.f;
        for (int j4 = 0; j4 < 10; ++j4) {
            int j = j4 * 4;
            float y0 = sm.yp[j][l], y1 = sm.yp[j + 1][l],
                  y2 = sm.yp[j + 2][l], y3 = sm.yp[j + 3][l];
#pragma unroll
            for (int r = 0; r < 8; ++r) {
                float4 av = *reinterpret_cast<const float4*>(&sm.a[w * 8 + r][j]);
                acc[r] += av.x * y0 + av.y * y1 + av.z * y2 + av.w * y3;
            }
        }
#pragma unroll
        for (int r = 0; r < 8; ++r) sm.h[w * 8 + r][l] = fmaxf(acc[r], 0.f);
    }
    __syncwarp();

    // hc = h @ V^T ; gate ; update x
    {
        float acc[8][4];
#pragma unroll
        for (int r = 0; r < 8; ++r)
#pragma unroll
            for (int q = 0; q < 4; ++q) acc[r][q] = 0.f;

        for (int k4 = 0; k4 < 8; ++k4) {
            int k = 4 * k4;
            float vv[4][4];
#pragma unroll
            for (int q = 0; q < 4; ++q) {
                int d = l + 32 * q;
                vv[q][0] = sm.V[d][k];     vv[q][1] = sm.V[d][k + 1];
                vv[q][2] = sm.V[d][k + 2]; vv[q][3] = sm.V[d][k + 3];
            }
#pragma unroll
            for (int r = 0; r < 8; ++r) {
                float4 hv = *reinterpret_cast<const float4*>(&sm.h[w * 8 + r][k]);
#pragma unroll
                for (int q = 0; q < 4; ++q)
                    acc[r][q] += hv.x * vv[q][0] + hv.y * vv[q][1] +
                                 hv.z * vv[q][2] + hv.w * vv[q][3];
            }
        }
        float gb = sm.gb;
#pragma unroll
        for (int r = 0; r < 8; ++r) {
            float gp = 0.f;
            float xv[4];
#pragma unroll
            for (int q = 0; q < 4; ++q) {
                int d = l + 32 * q;
                xv[q] = sm.xs[w * 8 + r][d];
                gp += xv[q] * sm.gw[d] + acc[r][q] * sm.gw[128 + d];
            }
#pragma unroll
            for (int o = 16; o; o >>= 1) gp += __shfl_xor_sync(0xffffffffu, gp, o);
            float z = 1.f / (1.f + __expf(-(gp + gb)));
            float* orow = g_x + (row0 + w * 8 + r) * 128;
#pragma unroll
            for (int q = 0; q < 4; ++q) {
                int d = l + 32 * q;
                orow[d] = (1.f - z) * xv[q] + z * acc[r][q];
            }
        }
    }
}

// =====================================================================
// K7: final — xp = relu(x@U); out = sigmoid(xp^T G xp)
// =====================================================================
struct SmF {
    float xs[64][128];
    float U[128][32];
    float G[32][32];
    float xp[64][36];
};

__global__ __launch_bounds__(256) void final_kernel(
    const float* __restrict__ Ug, float* __restrict__ out)
{
    extern __shared__ char smraw[];
    SmF& sm = *reinterpret_cast<SmF*>(smraw);
    const int t = threadIdx.x, w = t >> 5, l = t & 31;
    const size_t row0 = (size_t)blockIdx.x * 64;
    const int b = blockIdx.x >> 6;

#pragma unroll
    for (int u = 0; u < 8; ++u) {
        int id = t + 256 * u;
        int r = id >> 5, cq = id & 31;
        *reinterpret_cast<float4*>(&sm.xs[r][cq * 4]) =
            *reinterpret_cast<const float4*>(g_x + (row0 + r) * 128 + cq * 4);
    }
#pragma unroll
    for (int u = 0; u < 4; ++u) {
        int id = t + 256 * u;
        int c = id >> 3, kq = id & 7;
        *reinterpret_cast<float4*>(&sm.U[c][kq * 4]) =
            *reinterpret_cast<const float4*>(Ug + c * 32 + kq * 4);
    }
    {
        int k1 = t >> 3;
        *reinterpret_cast<float4*>(&sm.G[k1][(t & 7) * 4]) =
            *reinterpret_cast<const float4*>(g_G + b * 1024 + t * 4);
    }
    __syncthreads();

    {
        float acc[8];
#pragma unroll
        for (int r = 0; r < 8; ++r) acc[r] = 0.f;
        for (int c4 = 0; c4 < 32; ++c4) {
            int c = c4 * 4;
            float u0 = sm.U[c][l], u1 = sm.U[c + 1][l],
                  u2 = sm.U[c + 2][l], u3 = sm.U[c + 3][l];
#pragma unroll
            for (int r = 0; r < 8; ++r) {
                float4 xv = *reinterpret_cast<const float4*>(&sm.xs[w * 8 + r][c]);
                acc[r] += xv.x * u0 + xv.y * u1 + xv.z * u2 + xv.w * u3;
            }
        }
#pragma unroll
        for (int r = 0; r < 8; ++r) sm.xp[w * 8 + r][l] = fmaxf(acc[r], 0.f);
    }
    __syncwarp();

    {
        float acc[8];
#pragma unroll
        for (int r = 0; r < 8; ++r) acc[r] = 0.f;
        for (int k14 = 0; k14 < 8; ++k14) {
            int k1 = 4 * k14;
            float g0 = sm.G[k1][l], g1 = sm.G[k1 + 1][l],
                  g2 = sm.G[k1 + 2][l], g3 = sm.G[k1 + 3][l];
#pragma unroll
            for (int r = 0; r < 8; ++r) {
                float4 xv = *reinterpret_cast<const float4*>(&sm.xp[w * 8 + r][k1]);
                acc[r] += xv.x * g0 + xv.y * g1 + xv.z * g2 + xv.w * g3;
            }
        }
#pragma unroll
        for (int r = 0; r < 8; ++r) {
            float v = sm.xp[w * 8 + r][l] * acc[r];
#pragma unroll
            for (int o = 16; o; o >>= 1) v += __shfl_xor_sync(0xffffffffu, v, o);
            if (l == 0) out[row0 + w * 8 + r] = 1.f / (1.f + __expf(-v));
        }
    }
}

// =====================================================================
extern "C" void kernel_launch(void* const* d_in, const int* in_sizes, int n_in,
                              void* d_out, int out_size)
{
    const float* node = (const float*)d_in[0];
    const float* frag = (const float*)d_in[1];
    const float* Wg   = (const float*)d_in[2];
    const float* bg   = (const float*)d_in[3];
    const float* Ug   = (const float*)d_in[4];
    const float* Vg   = (const float*)d_in[5];
    const float* qg   = (const float*)d_in[6];
    const float* gW   = (const float*)d_in[7];
    const float* gB   = (const float*)d_in[8];
    float* out = (float*)d_out;

    cudaFuncSetAttribute(gemm_in_kernel, cudaFuncAttributeMaxDynamicSharedMemorySize, (int)sizeof(SmG));
    cudaFuncSetAttribute(layerA_kernel,  cudaFuncAttributeMaxDynamicSharedMemorySize, (int)sizeof(SmA));
    cudaFuncSetAttribute(layerB_kernel,  cudaFuncAttributeMaxDynamicSharedMemorySize, (int)sizeof(SmB));
    cudaFuncSetAttribute(final_kernel,   cudaFuncAttributeMaxDynamicSharedMemorySize, (int)sizeof(SmF));

    gemm_in_kernel<<<NBLKX, 256, sizeof(SmG)>>>(node, Wg, bg, 0);
    gemm_in_kernel<<<NBLKF, 256, sizeof(SmG)>>>(frag, Wg, bg, 1);
    stats_kernel<<<1, 256>>>();
    yp_kernel<<<BGR, 256>>>(Vg, qg);
    gram_kernel<<<BGR, 256>>>();
    layerA_kernel<<<NBLKX, 256, sizeof(SmA)>>>(Ug, 1);   // norm + writeback
    merge_kernel<<<BGR, 64>>>();
    layerB_kernel<<<NBLKX, 256, sizeof(SmB)>>>(Vg, gW, gB);
    layerA_kernel<<<NBLKX, 256, sizeof(SmA)>>>(Ug, 0);
    merge_kernel<<<BGR, 64>>>();
    layerB_kernel<<<NBLKX, 256, sizeof(SmB)>>>(Vg, gW, gB);
    final_kernel<<<NBLKX, 256, sizeof(SmF)>>>(Ug, out);
}

// round 7
// speedup vs baseline: 1.9453x; 1.2352x over previous
#include <cuda_runtime.h>
#include <math.h>

#define BGR   32
#define NTOT  131072
#define NBLKX 2048
#define NBLKF 20

typedef unsigned long long u64;
union F4 { float4 v; u64 u[2]; };

__device__ __forceinline__ void fma2(u64& d, u64 a, u64 b) {
    asm("fma.rn.f32x2 %0, %1, %2, %0;" : "+l"(d) : "l"(a), "l"(b));
}
__device__ __forceinline__ float hsum2(u64 a) {
    unsigned lo, hi;
    asm("mov.b64 {%0,%1}, %2;" : "=r"(lo), "=r"(hi) : "l"(a));
    return __uint_as_float(lo) + __uint_as_float(hi);
}

// ---------------- device scratch (no runtime alloc) ----------------
__device__ __align__(16) float g_x[(size_t)NTOT * 128];
__device__ __align__(16) float g_I[(size_t)NTOT * 40];
__device__ __align__(16) float g_ypre[1280 * 128];
__device__ __align__(16) float g_yp[BGR * 40 * 32];
__device__ __align__(16) float g_G[BGR * 32 * 32];
__device__ float g_part[NBLKX * 2];
__device__ float g_partf[NBLKF * 2];
__device__ float g_scal[4];
__device__ float g_sm[BGR * 64 * 40];
__device__ float g_ss[BGR * 64 * 40];
__device__ float g_m[BGR * 40];
__device__ float g_si[BGR * 40];

// =====================================================================
// K1: out[rows][128] = in[rows][64] @ W^T + b ; LN partial sums
// =====================================================================
struct SmG {
    float in_sh[64][68];   // 272B pitch (17x16B, odd); broadcast reads
    float Ws[128][68];     // lane-indexed d reads, LDS.128 conflict-free
    float bias[128];
    float red[16];
};

__global__ __launch_bounds__(256, 2) void gemm_in_kernel(
    const float* __restrict__ inp, const float* __restrict__ Wg,
    const float* __restrict__ bg, int sel)
{
    extern __shared__ char smraw[];
    SmG& sm = *reinterpret_cast<SmG*>(smraw);
    const int t = threadIdx.x, w = t >> 5, l = t & 31;
    const size_t row0 = (size_t)blockIdx.x * 64;
    float* outp  = sel ? g_ypre : g_x;
    float* partp = sel ? g_partf : g_part;

#pragma unroll
    for (int u = 0; u < 4; ++u) {
        int id = t + 256 * u;
        int r = id >> 4, cq = id & 15;
        *reinterpret_cast<float4*>(&sm.in_sh[r][cq * 4]) =
            *reinterpret_cast<const float4*>(inp + (row0 + r) * 64 + cq * 4);
    }
#pragma unroll
    for (int u = 0; u < 8; ++u) {           // W native [128][64], float4
        int id = t + 256 * u;
        int d = id >> 4, f4 = id & 15;
        *reinterpret_cast<float4*>(&sm.Ws[d][f4 * 4]) =
            *reinterpret_cast<const float4*>(Wg + d * 64 + f4 * 4);
    }
    if (t < 128) sm.bias[t] = bg[t];
    __syncthreads();

    u64 acc[8][4];
#pragma unroll
    for (int r = 0; r < 8; ++r)
#pragma unroll
        for (int q = 0; q < 4; ++q) acc[r][q] = 0ull;

#pragma unroll
    for (int f4 = 0; f4 < 16; ++f4) {
        int f = f4 * 4;
        F4 wq[4];
#pragma unroll
        for (int q = 0; q < 4; ++q)
            wq[q].v = *reinterpret_cast<const float4*>(&sm.Ws[l + 32 * q][f]);
#pragma unroll
        for (int r = 0; r < 8; ++r) {
            F4 xv; xv.v = *reinterpret_cast<const float4*>(&sm.in_sh[w * 8 + r][f]);
#pragma unroll
            for (int q = 0; q < 4; ++q) {
                fma2(acc[r][q], xv.u[0], wq[q].u[0]);
                fma2(acc[r][q], xv.u[1], wq[q].u[1]);
            }
        }
    }

    float s1 = 0.f, s2 = 0.f;
#pragma unroll
    for (int r = 0; r < 8; ++r) {
        float* orow = outp + (row0 + w * 8 + r) * 128;
#pragma unroll
        for (int q = 0; q < 4; ++q) {
            float v = hsum2(acc[r][q]) + sm.bias[l + 32 * q];
            orow[l + 32 * q] = v;
            s1 += v; s2 += v * v;
        }
    }
#pragma unroll
    for (int o = 16; o; o >>= 1) {
        s1 += __shfl_xor_sync(0xffffffffu, s1, o);
        s2 += __shfl_xor_sync(0xffffffffu, s2, o);
    }
    if (l == 0) { sm.red[w] = s1; sm.red[8 + w] = s2; }
    __syncthreads();
    if (t == 0) {
        float S = 0.f, Q = 0.f;
        for (int i = 0; i < 8; ++i) { S += sm.red[i]; Q += sm.red[8 + i]; }
        partp[2 * blockIdx.x]     = S;
        partp[2 * blockIdx.x + 1] = Q;
    }
}

// =====================================================================
// K2: finalize LN scalars
// =====================================================================
__global__ void stats_kernel()
{
    __shared__ double sh[256];
    const int t = threadIdx.x;
    double s = 0.0, q = 0.0;
    for (int i = t; i < NBLKX; i += 256) { s += (double)g_part[2 * i]; q += (double)g_part[2 * i + 1]; }

    double S, Q, Sf, Qf;
    sh[t] = s; __syncthreads();
    for (int o = 128; o; o >>= 1) { if (t < o) sh[t] += sh[t + o]; __syncthreads(); }
    S = sh[0]; __syncthreads();

    sh[t] = q; __syncthreads();
    for (int o = 128; o; o >>= 1) { if (t < o) sh[t] += sh[t + o]; __syncthreads(); }
    Q = sh[0]; __syncthreads();

    sh[t] = (t < NBLKF) ? (double)g_partf[2 * t] : 0.0; __syncthreads();
    for (int o = 128; o; o >>= 1) { if (t < o) sh[t] += sh[t + o]; __syncthreads(); }
    Sf = sh[0]; __syncthreads();

    sh[t] = (t < NBLKF) ? (double)g_partf[2 * t + 1] : 0.0; __syncthreads();
    for (int o = 128; o; o >>= 1) { if (t < o) sh[t] += sh[t + o]; __syncthreads(); }
    Qf = sh[0];

    if (t == 0) {
        double nx = 16777216.0;
        double mx = S / nx, vx = Q / nx - mx * mx;
        g_scal[0] = (float)mx;
        g_scal[1] = (float)(1.0 / sqrt(vx + 1e-5));
        double ny = 163840.0;
        double my = Sf / ny, vy = Qf / ny - my * my;
        g_scal[2] = (float)my;
        g_scal[3] = (float)(1.0 / sqrt(vy + 1e-5));
    }
}

// =====================================================================
// K3: per graph: y_p = relu(q * relu(LN(ys) @ V)) ; G = y_p^T y_p
// =====================================================================
__global__ __launch_bounds__(256) void yp_kernel(
    const float* __restrict__ Vg, const float* __restrict__ qg)
{
    __shared__ float ys[40][128];
    __shared__ float Vt[32][132];    // V transposed [k][c], c<128 (pitch 132!)
    __shared__ float yps[40][36];
    __shared__ float qs[32];
    const int b = blockIdx.x, t = threadIdx.x;
    const float m = g_scal[2], rs = g_scal[3];
    for (int i = t; i < 5120; i += 256)
        ys[i >> 7][i & 127] = (g_ypre[b * 5120 + i] - m) * rs;
#pragma unroll
    for (int u = 0; u < 16; ++u) {
        int id = t + 256 * u;
        Vt[id & 31][id >> 5] = Vg[id];
    }
    if (t < 32) qs[t] = qg[t];
    __syncthreads();
#pragma unroll
    for (int u = 0; u < 5; ++u) {
        int id = t + 256 * u;
        int j = id >> 5, k = id & 31;
        u64 acc = 0ull;
#pragma unroll
        for (int c4 = 0; c4 < 32; ++c4) {
            F4 yv; yv.v = *reinterpret_cast<const float4*>(&ys[j][c4 * 4]);
            F4 vv; vv.v = *reinterpret_cast<const float4*>(&Vt[k][c4 * 4]);
            fma2(acc, yv.u[0], vv.u[0]);
            fma2(acc, yv.u[1], vv.u[1]);
        }
        float a = fmaxf(hsum2(acc), 0.f);
        a = fmaxf(qs[k] * a, 0.f);
        yps[j][k] = a;
        g_yp[b * 1280 + id] = a;
    }
    __syncthreads();
#pragma unroll
    for (int u = 0; u < 4; ++u) {
        int id = t + 256 * u;
        int k1 = id >> 5, k2 = id & 31;
        float acc = 0.f;
#pragma unroll
        for (int j = 0; j < 40; ++j) acc += yps[j][k1] * yps[j][k2];
        g_G[b * 1024 + id] = acc;
    }
}

// =====================================================================
// K4: layerA — (optional norm+writeback), xp = relu(x@U), I = xp@yp^T,
//              per-tile softmax partials
// =====================================================================
struct SmA {
    float xs[64][128];
    float Ut[32][132];     // U transposed [k][c], c<128 (pitch 132!)
    float yp[40][36];
    float xp[64][36];
    float red_m[8][40];
    float red_s[8][40];
};

__global__ __launch_bounds__(256, 3) void layerA_kernel(const float* __restrict__ Ug,
                                                        int do_norm)
{
    extern __shared__ char smraw[];
    SmA& sm = *reinterpret_cast<SmA*>(smraw);
    const int t = threadIdx.x, w = t >> 5, l = t & 31;
    const size_t row0 = (size_t)blockIdx.x * 64;
    const int b = blockIdx.x >> 6, blk = blockIdx.x & 63;

    if (do_norm) {
        const float m = g_scal[0], rs = g_scal[1];
#pragma unroll
        for (int u = 0; u < 8; ++u) {
            int id = t + 256 * u;
            int r = id >> 5, cq = id & 31;
            float* gp = g_x + (row0 + r) * 128 + cq * 4;
            float4 v = *reinterpret_cast<const float4*>(gp);
            v.x = (v.x - m) * rs; v.y = (v.y - m) * rs;
            v.z = (v.z - m) * rs; v.w = (v.w - m) * rs;
            *reinterpret_cast<float4*>(gp) = v;
            *reinterpret_cast<float4*>(&sm.xs[r][cq * 4]) = v;
        }
    } else {
#pragma unroll
        for (int u = 0; u < 8; ++u) {
            int id = t + 256 * u;
            int r = id >> 5, cq = id & 31;
            *reinterpret_cast<float4*>(&sm.xs[r][cq * 4]) =
                *reinterpret_cast<const float4*>(g_x + (row0 + r) * 128 + cq * 4);
        }
    }
#pragma unroll
    for (int u = 0; u < 16; ++u) {          // U [c][k] -> Ut[k][c]
        int id = t + 256 * u;
        sm.Ut[id & 31][id >> 5] = Ug[id];
    }
#pragma unroll
    for (int u = 0; u < 5; ++u) {
        int id = t + 256 * u;
        sm.yp[id >> 5][id & 31] = g_yp[b * 1280 + id];
    }
    __syncthreads();

    // xp = relu(x @ U); lane owns k=l; f32x2 over c
    {
        u64 acc[8];
#pragma unroll
        for (int r = 0; r < 8; ++r) acc[r] = 0ull;
#pragma unroll
        for (int c4 = 0; c4 < 32; ++c4) {
            int c = c4 * 4;
            F4 uv; uv.v = *reinterpret_cast<const float4*>(&sm.Ut[l][c]);
#pragma unroll
            for (int r = 0; r < 8; ++r) {
                F4 xv; xv.v = *reinterpret_cast<const float4*>(&sm.xs[w * 8 + r][c]);
                fma2(acc[r], xv.u[0], uv.u[0]);
                fma2(acc[r], xv.u[1], uv.u[1]);
            }
        }
#pragma unroll
        for (int r = 0; r < 8; ++r) sm.xp[w * 8 + r][l] = fmaxf(hsum2(acc[r]), 0.f);
    }
    __syncwarp();

    // I = xp @ yp^T; lane handles j0=l and (if l<8) j1=l+32; f32x2 over k
    {
        const int j0 = l;
        const bool has1 = (l < 8);
        const int j1 = has1 ? (l + 32) : 39;
        u64 a0[8], a1[8];
#pragma unroll
        for (int r = 0; r < 8; ++r) { a0[r] = 0ull; a1[r] = 0ull; }
#pragma unroll
        for (int k4 = 0; k4 < 8; ++k4) {
            int k = k4 * 4;
            F4 y0; y0.v = *reinterpret_cast<const float4*>(&sm.yp[j0][k]);
            F4 y1; y1.v = *reinterpret_cast<const float4*>(&sm.yp[j1][k]);
#pragma unroll
            for (int r = 0; r < 8; ++r) {
                F4 xv; xv.v = *reinterpret_cast<const float4*>(&sm.xp[w * 8 + r][k]);
                fma2(a0[r], xv.u[0], y0.u[0]);
                fma2(a0[r], xv.u[1], y0.u[1]);
                fma2(a1[r], xv.u[0], y1.u[0]);
                fma2(a1[r], xv.u[1], y1.u[1]);
            }
        }
        float i0[8], i1[8];
#pragma unroll
        for (int r = 0; r < 8; ++r) { i0[r] = hsum2(a0[r]); i1[r] = hsum2(a1[r]); }
        float m0 = -1e30f, m1 = -1e30f;
#pragma unroll
        for (int r = 0; r < 8; ++r) { m0 = fmaxf(m0, i0[r]); m1 = fmaxf(m1, i1[r]); }
        float s0 = 0.f, s1v = 0.f;
#pragma unroll
        for (int r = 0; r < 8; ++r) { s0 += __expf(i0[r] - m0); s1v += __expf(i1[r] - m1); }
#pragma unroll
        for (int r = 0; r < 8; ++r) {
            size_t row = row0 + w * 8 + r;
            g_I[row * 40 + j0] = i0[r];
            if (has1) g_I[row * 40 + j1] = i1[r];
        }
        sm.red_m[w][j0] = m0; sm.red_s[w][j0] = s0;
        if (has1) { sm.red_m[w][j1] = m1; sm.red_s[w][j1] = s1v; }
    }
    __syncthreads();

    if (t < 40) {
        float m = sm.red_m[0][t], s = sm.red_s[0][t];
#pragma unroll
        for (int ww = 1; ww < 8; ++ww) {
            float bm = sm.red_m[ww][t], bs = sm.red_s[ww][t];
            float mn = fmaxf(m, bm);
            s = s * __expf(m - mn) + bs * __expf(bm - mn);
            m = mn;
        }
        int idx = (b * 64 + blk) * 40 + t;
        g_sm[idx] = m; g_ss[idx] = s;
    }
}

// =====================================================================
// K5: merge softmax partials
// =====================================================================
__global__ void merge_kernel()
{
    const int b = blockIdx.x, t = threadIdx.x;
    if (t >= 40) return;
    float m = -1e30f, s = 0.f;
    for (int blk = 0; blk < 64; ++blk) {
        int idx = (b * 64 + blk) * 40 + t;
        float bm = g_sm[idx], bs = g_ss[idx];
        float mn = fmaxf(m, bm);
        s = s * __expf(m - mn) + bs * __expf(bm - mn);
        m = mn;
    }
    g_m[b * 40 + t]  = m;
    g_si[b * 40 + t] = 1.f / s;
}

// =====================================================================
// K6: layerB — A, h=relu(A@yp), hc=h@V^T, gate, x-update
// =====================================================================
struct SmB {
    float xs[64][128];
    float a[64][44];
    float ypT[32][44];
    float Vs[128][36];
    float h[64][36];
    float gw[256];
    float gb;
};

__global__ __launch_bounds__(256, 2) void layerB_kernel(
    const float* __restrict__ Vg, const float* __restrict__ gWp,
    const float* __restrict__ gBp)
{
    extern __shared__ char smraw[];
    SmB& sm = *reinterpret_cast<SmB*>(smraw);
    const int t = threadIdx.x, w = t >> 5, l = t & 31;
    const size_t row0 = (size_t)blockIdx.x * 64;
    const int b = blockIdx.x >> 6;

#pragma unroll
    for (int u = 0; u < 8; ++u) {
        int id = t + 256 * u;
        int r = id >> 5, cq = id & 31;
        *reinterpret_cast<float4*>(&sm.xs[r][cq * 4]) =
            *reinterpret_cast<const float4*>(g_x + (row0 + r) * 128 + cq * 4);
    }
#pragma unroll
    for (int u = 0; u < 4; ++u) {           // V native [128][32], float4
        int id = t + 256 * u;
        int d = id >> 3, k4 = id & 7;
        *reinterpret_cast<float4*>(&sm.Vs[d][k4 * 4]) =
            *reinterpret_cast<const float4*>(Vg + d * 32 + k4 * 4);
    }
#pragma unroll
    for (int u = 0; u < 5; ++u) {           // yp [j][k] -> ypT[k][j]
        int id = t + 256 * u;
        sm.ypT[id & 31][id >> 5] = g_yp[b * 1280 + id];
    }
    sm.gw[t] = gWp[t];
    if (t == 0) sm.gb = gBp[0];
#pragma unroll
    for (int u = 0; u < 10; ++u) {
        int id = t + 256 * u;
        int r = id / 40, j = id - r * 40;
        float v = g_I[row0 * 40 + id];
        sm.a[r][j] = __expf(v - g_m[b * 40 + j]) * g_si[b * 40 + j];
    }
    __syncthreads();

    // h = relu(A @ yp); lane owns k=l; f32x2 over j
    {
        u64 acc[8];
#pragma unroll
        for (int r = 0; r < 8; ++r) acc[r] = 0ull;
#pragma unroll
        for (int j4 = 0; j4 < 10; ++j4) {
            int j = j4 * 4;
            F4 yv; yv.v = *reinterpret_cast<const float4*>(&sm.ypT[l][j]);
#pragma unroll
            for (int r = 0; r < 8; ++r) {
                F4 av; av.v = *reinterpret_cast<const float4*>(&sm.a[w * 8 + r][j]);
                fma2(acc[r], av.u[0], yv.u[0]);
                fma2(acc[r], av.u[1], yv.u[1]);
            }
        }
#pragma unroll
        for (int r = 0; r < 8; ++r) sm.h[w * 8 + r][l] = fmaxf(hsum2(acc[r]), 0.f);
    }
    __syncwarp();

    // hc = h @ V^T ; gate ; update x  (f32x2 over k)
    {
        u64 acc[8][4];
#pragma unroll
        for (int r = 0; r < 8; ++r)
#pragma unroll
            for (int q = 0; q < 4; ++q) acc[r][q] = 0ull;

#pragma unroll
        for (int k4 = 0; k4 < 8; ++k4) {
            int k = 4 * k4;
            F4 vq[4];
#pragma unroll
            for (int q = 0; q < 4; ++q)
                vq[q].v = *reinterpret_cast<const float4*>(&sm.Vs[l + 32 * q][k]);
#pragma unroll
            for (int r = 0; r < 8; ++r) {
                F4 hv; hv.v = *reinterpret_cast<const float4*>(&sm.h[w * 8 + r][k]);
#pragma unroll
                for (int q = 0; q < 4; ++q) {
                    fma2(acc[r][q], hv.u[0], vq[q].u[0]);
                    fma2(acc[r][q], hv.u[1], vq[q].u[1]);
                }
            }
        }
        float gb = sm.gb;
#pragma unroll
        for (int r = 0; r < 8; ++r) {
            float gp = 0.f;
            float xv[4], hc[4];
#pragma unroll
            for (int q = 0; q < 4; ++q) {
                int d = l + 32 * q;
                hc[q] = hsum2(acc[r][q]);
                xv[q] = sm.xs[w * 8 + r][d];
                gp += xv[q] * sm.gw[d] + hc[q] * sm.gw[128 + d];
            }
#pragma unroll
            for (int o = 16; o; o >>= 1) gp += __shfl_xor_sync(0xffffffffu, gp, o);
            float z = 1.f / (1.f + __expf(-(gp + gb)));
            float* orow = g_x + (row0 + w * 8 + r) * 128;
#pragma unroll
            for (int q = 0; q < 4; ++q) {
                int d = l + 32 * q;
                orow[d] = (1.f - z) * xv[q] + z * hc[q];
            }
        }
    }
}

// =====================================================================
// K7: final — xp = relu(x@U); out = sigmoid(xp^T G xp)  (G symmetric)
// =====================================================================
struct SmF {
    float xs[64][128];
    float Ut[32][132];     // pitch 132!
    float G[32][36];
    float xp[64][36];
};

__global__ __launch_bounds__(256, 3) void final_kernel(
    const float* __restrict__ Ug, float* __restrict__ out)
{
    extern __shared__ char smraw[];
    SmF& sm = *reinterpret_cast<SmF*>(smraw);
    const int t = threadIdx.x, w = t >> 5, l = t & 31;
    const size_t row0 = (size_t)blockIdx.x * 64;
    const int b = blockIdx.x >> 6;

#pragma unroll
    for (int u = 0; u < 8; ++u) {
        int id = t + 256 * u;
        int r = id >> 5, cq = id & 31;
        *reinterpret_cast<float4*>(&sm.xs[r][cq * 4]) =
            *reinterpret_cast<const float4*>(g_x + (row0 + r) * 128 + cq * 4);
    }
#pragma unroll
    for (int u = 0; u < 16; ++u) {
        int id = t + 256 * u;
        sm.Ut[id & 31][id >> 5] = Ug[id];
    }
#pragma unroll
    for (int u = 0; u < 4; ++u) {
        int id = t + 256 * u;
        int k1 = id >> 5, k2 = id & 31;
        sm.G[k1][k2] = g_G[b * 1024 + id];
    }
    __syncthreads();

    {
        u64 acc[8];
#pragma unroll
        for (int r = 0; r < 8; ++r) acc[r] = 0ull;
#pragma unroll
        for (int c4 = 0; c4 < 32; ++c4) {
            int c = c4 * 4;
            F4 uv; uv.v = *reinterpret_cast<const float4*>(&sm.Ut[l][c]);
#pragma unroll
            for (int r = 0; r < 8; ++r) {
                F4 xv; xv.v = *reinterpret_cast<const float4*>(&sm.xs[w * 8 + r][c]);
                fma2(acc[r], xv.u[0], uv.u[0]);
                fma2(acc[r], xv.u[1], uv.u[1]);
            }
        }
#pragma unroll
        for (int r = 0; r < 8; ++r) sm.xp[w * 8 + r][l] = fmaxf(hsum2(acc[r]), 0.f);
    }
    __syncwarp();

    {
        u64 acc[8];
#pragma unroll
        for (int r = 0; r < 8; ++r) acc[r] = 0ull;
#pragma unroll
        for (int k14 = 0; k14 < 8; ++k14) {
            int k1 = 4 * k14;
            F4 gv; gv.v = *reinterpret_cast<const float4*>(&sm.G[l][k1]);  // symmetric
#pragma unroll
            for (int r = 0; r < 8; ++r) {
                F4 xv; xv.v = *reinterpret_cast<const float4*>(&sm.xp[w * 8 + r][k1]);
                fma2(acc[r], xv.u[0], gv.u[0]);
                fma2(acc[r], xv.u[1], gv.u[1]);
            }
        }
#pragma unroll
        for (int r = 0; r < 8; ++r) {
            float v = sm.xp[w * 8 + r][l] * hsum2(acc[r]);
#pragma unroll
            for (int o = 16; o; o >>= 1) v += __shfl_xor_sync(0xffffffffu, v, o);
            if (l == 0) out[row0 + w * 8 + r] = 1.f / (1.f + __expf(-v));
        }
    }
}

// =====================================================================
extern "C" void kernel_launch(void* const* d_in, const int* in_sizes, int n_in,
                              void* d_out, int out_size)
{
    const float* node = (const float*)d_in[0];
    const float* frag = (const float*)d_in[1];
    const float* Wg   = (const float*)d_in[2];
    const float* bg   = (const float*)d_in[3];
    const float* Ug   = (const float*)d_in[4];
    const float* Vg   = (const float*)d_in[5];
    const float* qg   = (const float*)d_in[6];
    const float* gW   = (const float*)d_in[7];
    const float* gB   = (const float*)d_in[8];
    float* out = (float*)d_out;

    cudaFuncSetAttribute(gemm_in_kernel, cudaFuncAttributeMaxDynamicSharedMemorySize, (int)sizeof(SmG));
    cudaFuncSetAttribute(layerA_kernel,  cudaFuncAttributeMaxDynamicSharedMemorySize, (int)sizeof(SmA));
    cudaFuncSetAttribute(layerB_kernel,  cudaFuncAttributeMaxDynamicSharedMemorySize, (int)sizeof(SmB));
    cudaFuncSetAttribute(final_kernel,   cudaFuncAttributeMaxDynamicSharedMemorySize, (int)sizeof(SmF));

    gemm_in_kernel<<<NBLKX, 256, sizeof(SmG)>>>(node, Wg, bg, 0);
    gemm_in_kernel<<<NBLKF, 256, sizeof(SmG)>>>(frag, Wg, bg, 1);
    stats_kernel<<<1, 256>>>();
    yp_kernel<<<BGR, 256>>>(Vg, qg);
    layerA_kernel<<<NBLKX, 256, sizeof(SmA)>>>(Ug, 1);   // norm + writeback
    merge_kernel<<<BGR, 64>>>();
    layerB_kernel<<<NBLKX, 256, sizeof(SmB)>>>(Vg, gW, gB);
    layerA_kernel<<<NBLKX, 256, sizeof(SmA)>>>(Ug, 0);
    merge_kernel<<<BGR, 64>>>();
    layerB_kernel<<<NBLKX, 256, sizeof(SmB)>>>(Vg, gW, gB);
    final_kernel<<<NBLKX, 256, sizeof(SmF)>>>(Ug, out);
}